// round 3
// baseline (speedup 1.0000x reference)
#include <cuda_runtime.h>
#include <math.h>

// Problem constants
#define N_VEC   65536      // 64*32*32 vectors
#define DIM     256
#define KCODES  2048
#define RT      128        // rows per block
#define CT      128        // codes per K-tile
#define DT      32         // D chunk through smem

// Output layout (all float32, concatenated in reference return order)
#define OFF_LOSS  0
#define OFF_QUANT 1
#define OFF_PERP  (1 + 64*256*32*32)     // 4194305
#define OFF_IDX   (OFF_PERP + 1)         // 4194306

// Device scratch (static allocation — no runtime allocs)
__device__ float g_cbT[DIM * KCODES];    // codebook transposed [d][k]
__device__ float g_csq[KCODES];          // ||c_k||^2
__device__ float g_xsq[N_VEC];           // ||x_n||^2
__device__ int   g_idx[N_VEC];
__device__ unsigned long long g_sse;     // fixed-point (x256) SSE accumulator
__device__ int   g_cnt[KCODES];

// ---------------------------------------------------------------------------
__global__ void k_init()
{
    int t = blockIdx.x * 256 + threadIdx.x;
    if (t == 0) g_sse = 0ULL;
    if (t < KCODES) g_cnt[t] = 0;
}

// Transpose codebook [K][D] -> g_cbT [D][K] (32x32 smem tiles, conflict-free)
__global__ void k_transpose(const float* __restrict__ cb)
{
    __shared__ float tile[32][33];
    int k0 = blockIdx.x * 32, d0 = blockIdx.y * 32;
    int tx = threadIdx.x, ty = threadIdx.y;   // 32x8
#pragma unroll
    for (int i = ty; i < 32; i += 8)
        tile[i][tx] = cb[(size_t)(k0 + i) * DIM + d0 + tx];
    __syncthreads();
#pragma unroll
    for (int i = ty; i < 32; i += 8)
        g_cbT[(size_t)(d0 + i) * KCODES + k0 + tx] = tile[tx][i];
}

// ||c_k||^2
__global__ void k_csq(const float* __restrict__ cb)
{
    int k = blockIdx.x * 256 + threadIdx.x;
    const float4* p = (const float4*)(cb + (size_t)k * DIM);
    float s = 0.f;
#pragma unroll 8
    for (int i = 0; i < DIM / 4; ++i) {
        float4 v = p[i];
        s += v.x * v.x + v.y * v.y + v.z * v.z + v.w * v.w;
    }
    g_csq[k] = s;
}

// ||x_n||^2 — block of 128 threads handles 128 consecutive rows (coalesced over d)
__global__ void k_xsq(const float* __restrict__ inp)
{
    int row0 = blockIdx.x * RT;
    int b = row0 >> 10, rem0 = row0 & 1023;
    const float* base = inp + (size_t)b * 262144 + rem0 + threadIdx.x;
    float s = 0.f;
#pragma unroll 8
    for (int d = 0; d < DIM; ++d) {
        float v = base[(size_t)d * 1024];
        s += v * v;
    }
    g_xsq[row0 + threadIdx.x] = s;
}

// ---------------------------------------------------------------------------
// Fused GEMM + argmin. Block: 256 threads (16x16), 128 rows x 128-code K-tiles,
// per-thread 8x8 fp32 accumulator. Both smem tiles d-major [d][128] so all
// fragment loads are contiguous LDS.128 (conflict-free, no transposes).
__global__ __launch_bounds__(256, 2)
void k_argmin(const float* __restrict__ inp, float* __restrict__ out)
{
    __shared__ float xs[DT][RT];
    __shared__ float cs[DT][CT];
    __shared__ float bestv[RT];
    __shared__ int   besti[RT];

    int tid = threadIdx.x;
    int tx = tid & 15, ty = tid >> 4;
    int row0 = blockIdx.x * RT;
    int b = row0 >> 10, rem0 = row0 & 1023;
    const float* xbase = inp + (size_t)b * 262144 + rem0;

    if (tid < RT) { bestv[tid] = 3.4e38f; besti[tid] = 0; }

    float s1v[8];
#pragma unroll
    for (int i = 0; i < 8; ++i) s1v[i] = g_xsq[row0 + ty * 8 + i];

    for (int kt = 0; kt < KCODES / CT; ++kt) {
        float acc[8][8];
#pragma unroll
        for (int i = 0; i < 8; ++i)
#pragma unroll
            for (int j = 0; j < 8; ++j) acc[i][j] = 0.f;

        const float* ct = g_cbT + kt * CT;

        for (int dt = 0; dt < DIM / DT; ++dt) {
            __syncthreads();
            // load 32x128 of X and C^T: 1024 float4 each, 4 per thread
#pragma unroll
            for (int i = 0; i < 4; ++i) {
                int li = tid + i * 256;
                int d = li >> 5, c4 = (li & 31) << 2;
                *(float4*)&xs[d][c4] =
                    *(const float4*)&xbase[(size_t)(dt * DT + d) * 1024 + c4];
                *(float4*)&cs[d][c4] =
                    *(const float4*)&ct[(size_t)(dt * DT + d) * KCODES + c4];
            }
            __syncthreads();
#pragma unroll 8
            for (int d = 0; d < DT; ++d) {
                float a[8], bb[8];
                *(float4*)&a[0]  = *(const float4*)&xs[d][ty * 8];
                *(float4*)&a[4]  = *(const float4*)&xs[d][ty * 8 + 4];
                *(float4*)&bb[0] = *(const float4*)&cs[d][tx * 8];
                *(float4*)&bb[4] = *(const float4*)&cs[d][tx * 8 + 4];
#pragma unroll
                for (int i = 0; i < 8; ++i)
#pragma unroll
                    for (int j = 0; j < 8; ++j)
                        acc[i][j] = fmaf(a[i], bb[j], acc[i][j]);
            }
        }

        // epilogue: dist = fl(fl(s1 + s2) - 2*m), argmin with first-index ties
        float csq8[8];
#pragma unroll
        for (int j = 0; j < 8; ++j) csq8[j] = g_csq[kt * CT + tx * 8 + j];

#pragma unroll
        for (int i = 0; i < 8; ++i) {
            float v = 3.4e38f; int c = 0;
#pragma unroll
            for (int j = 0; j < 8; ++j) {
                float A  = __fadd_rn(s1v[i], csq8[j]);
                float dd = __fsub_rn(A, 2.0f * acc[i][j]);
                int code = kt * CT + tx * 8 + j;
                if (dd < v) { v = dd; c = code; }
            }
            // reduce across the 16 lanes sharing this row group
#pragma unroll
            for (int m = 8; m; m >>= 1) {
                float ov = __shfl_xor_sync(0xffffffffu, v, m);
                int   oc = __shfl_xor_sync(0xffffffffu, c, m);
                if (ov < v || (ov == v && oc < c)) { v = ov; c = oc; }
            }
            if (tx == 0) {
                int r = ty * 8 + i;
                if (v < bestv[r]) { bestv[r] = v; besti[r] = c; }
            }
        }
    }
    __syncthreads();
    if (tid < RT) {
        int gi = besti[tid];
        g_idx[row0 + tid] = gi;
        out[OFF_IDX + row0 + tid] = (float)gi;
    }
}

// ---------------------------------------------------------------------------
// Gather quantized vectors (straight-through, replicating reference rounding),
// write quant_out in [B,D,H,W] layout, accumulate SSE for the loss.
__global__ void k_gather(const float* __restrict__ inp,
                         const float* __restrict__ cb,
                         float* __restrict__ out)
{
    __shared__ int   sidx[RT];
    __shared__ float red[256];
    int tid = threadIdx.x;
    int row0 = blockIdx.x * RT;
    if (tid < RT) sidx[tid] = g_idx[row0 + tid];
    __syncthreads();

    int b = row0 >> 10, rem0 = row0 & 1023;
    size_t base = (size_t)b * 262144 + rem0;
    int r  = tid & 127;
    int d0 = tid >> 7;   // 0 or 1
    const float* crow = cb + (size_t)sidx[r] * DIM;

    float s = 0.f;
#pragma unroll 4
    for (int d = d0; d < DIM; d += 2) {
        float q = __ldg(&crow[d]);
        size_t off = base + (size_t)d * 1024 + r;
        float x = inp[off];
        out[OFF_QUANT + off] = __fadd_rn(x, __fsub_rn(q, x));  // x + (q - x)
        float df = __fsub_rn(q, x);
        s = fmaf(df, df, s);
    }
    red[tid] = s;
    __syncthreads();
    for (int m = 128; m; m >>= 1) {
        if (tid < m) red[tid] += red[tid + m];
        __syncthreads();
    }
    if (tid == 0) {
        double v = (double)red[0] * 256.0;
        atomicAdd(&g_sse, (unsigned long long)(v + 0.5));  // deterministic fixed-point
    }
}

__global__ void k_hist()
{
    __shared__ int h[KCODES];
    for (int i = threadIdx.x; i < KCODES; i += 256) h[i] = 0;
    __syncthreads();
    for (int i = blockIdx.x * 256 + threadIdx.x; i < N_VEC; i += gridDim.x * 256)
        atomicAdd(&h[g_idx[i]], 1);
    __syncthreads();
    for (int i = threadIdx.x; i < KCODES; i += 256) {
        int c = h[i];
        if (c) atomicAdd(&g_cnt[i], c);
    }
}

__global__ void k_final(float* __restrict__ out)
{
    __shared__ float red[256];
    int tid = threadIdx.x;
    float s = 0.f;
    for (int k = tid; k < KCODES; k += 256) {
        float p = (float)g_cnt[k] * (1.0f / 65536.0f);
        s += p * logf(p + 1e-10f);
    }
    red[tid] = s;
    __syncthreads();
    for (int m = 128; m; m >>= 1) {
        if (tid < m) red[tid] += red[tid + m];
        __syncthreads();
    }
    if (tid == 0) {
        double sse = (double)g_sse * (1.0 / 256.0);
        out[OFF_LOSS] = (float)(1.25 * sse / 16777216.0);
        out[OFF_PERP] = expf(-red[0]);
    }
}

// ---------------------------------------------------------------------------
extern "C" void kernel_launch(void* const* d_in, const int* in_sizes, int n_in,
                              void* d_out, int out_size)
{
    const float* inp = (const float*)d_in[0];   // [64,256,32,32] f32
    const float* cb  = (const float*)d_in[1];   // [2048,256] f32
    float* out = (float*)d_out;

    k_init<<<8, 256>>>();
    k_transpose<<<dim3(64, 8), dim3(32, 8)>>>(cb);
    k_csq<<<8, 256>>>(cb);
    k_xsq<<<512, 128>>>(inp);
    k_argmin<<<512, 256>>>(inp, out);
    k_gather<<<512, 256>>>(inp, cb, out);
    k_hist<<<64, 256>>>();
    k_final<<<1, 256>>>(out);
}

// round 7
// speedup vs baseline: 2.2015x; 2.2015x over previous
#include <cuda_runtime.h>
#include <cuda_bf16.h>
#include <math.h>
#include <stdint.h>

// ===========================================================================
// Problem constants
#define N_VEC   65536      // 64*32*32 vectors
#define DIM     256
#define KCODES  2048

// Output layout (float32, reference return order)
#define OFF_LOSS  0
#define OFF_QUANT 1
#define OFF_PERP  (1 + 64*256*32*32)     // 4194305
#define OFF_IDX   (OFF_PERP + 1)         // 4194306

// ===========================================================================
// PTX helpers (base sm_100-legal: mma.sync / ldmatrix / cp.async only)
__device__ __forceinline__ uint32_t smem_to_u32(const void* p) {
    uint32_t a;
    asm("{ .reg .u64 t; cvta.to.shared.u64 t, %1; cvt.u32.u64 %0, t; }" : "=r"(a) : "l"(p));
    return a;
}
#define CP_ASYNC16(smem_u32, gptr) \
    asm volatile("cp.async.cg.shared.global [%0], [%1], 16;" :: "r"(smem_u32), "l"(gptr) : "memory")
#define CP_COMMIT() asm volatile("cp.async.commit_group;" ::: "memory")
#define CP_WAIT1()  asm volatile("cp.async.wait_group 1;" ::: "memory")

#define LDM_X4(r0, r1, r2, r3, addr) \
    asm volatile("ldmatrix.sync.aligned.m8n8.x4.shared.b16 {%0,%1,%2,%3}, [%4];" \
        : "=r"(r0), "=r"(r1), "=r"(r2), "=r"(r3) : "r"(addr))

#define MMA_BF16(d, a0, a1, a2, a3, b0, b1) \
    asm volatile("mma.sync.aligned.m16n8k16.row.col.f32.bf16.bf16.f32 " \
        "{%0,%1,%2,%3}, {%4,%5,%6,%7}, {%8,%9}, {%0,%1,%2,%3};" \
        : "+f"((d)[0]), "+f"((d)[1]), "+f"((d)[2]), "+f"((d)[3]) \
        : "r"(a0), "r"(a1), "r"(a2), "r"(a3), "r"(b0), "r"(b1))

// ===========================================================================
// Device scratch (static — no runtime allocation)
__device__ __nv_bfloat16 g_cbHi[KCODES * DIM];   // [code][k] row-major, hi split
__device__ __nv_bfloat16 g_cbLo[KCODES * DIM];   // [code][k] row-major, lo split
__device__ float g_csq[KCODES];                  // ||c_k||^2 (fp32)
__device__ float g_xsq[N_VEC];                   // ||x_n||^2 (serial fp32)
__device__ int   g_idx[N_VEC];
__device__ unsigned long long g_sse;
__device__ int   g_cnt[KCODES];

// ===========================================================================
__global__ void k_init()
{
    int t = blockIdx.x * 256 + threadIdx.x;
    if (t == 0) g_sse = 0ULL;
    if (t < KCODES) g_cnt[t] = 0;
}

// Split codebook into bf16 hi/lo, plain [code][k] layout.
__global__ void k_split(const float* __restrict__ cb)
{
    int code = blockIdx.x;     // 0..2047
    int d    = threadIdx.x;    // 0..255
    float x = cb[code * DIM + d];
    __nv_bfloat16 h = __float2bfloat16(x);
    __nv_bfloat16 l = __float2bfloat16(x - __bfloat162float(h));
    g_cbHi[code * DIM + d] = h;
    g_cbLo[code * DIM + d] = l;
}

// ||c_k||^2 in fp32
__global__ void k_csq(const float* __restrict__ cb)
{
    int k = blockIdx.x * 256 + threadIdx.x;
    const float4* p = (const float4*)(cb + (size_t)k * DIM);
    float s = 0.f;
#pragma unroll 8
    for (int i = 0; i < DIM / 4; ++i) {
        float4 v = p[i];
        s += v.x * v.x + v.y * v.y + v.z * v.z + v.w * v.w;
    }
    g_csq[k] = s;
}

// ||x_n||^2 — serial per-row fmaf, same order as the measured-flip-free R3.
__global__ void k_xsq(const float* __restrict__ inp)
{
    int row0 = blockIdx.x * 128;
    int b = row0 >> 10, rem0 = row0 & 1023;
    const float* base = inp + (size_t)b * 262144 + rem0 + threadIdx.x;
    float s = 0.f;
#pragma unroll 8
    for (int d = 0; d < DIM; ++d) {
        float v = base[(size_t)d * 1024];
        s = fmaf(v, v, s);
    }
    g_xsq[row0 + threadIdx.x] = s;
}

// ===========================================================================
// Fused bf16-split (Ootomo 3-pass) mma.sync GEMM + argmin.
// Block: 256 thr / 8 warps; 128 rows x all 2048 codes; warp w = rows [16w,16w+16).
// A resident in smem as bf16 hi/lo (padded stride 264 bf16 = 528B).
// B double-buffered: per stage [2 splits][128 codes][64 k], 144B padded rows.
// 64 stages: stage s -> code tile (s>>2), k-chunk (s&3).
#define A_STRIDE_E 264              // bf16 elems per A row (256 + 8 pad)
#define A_STRIDE_B 528
#define A_SPLIT_B  (128 * A_STRIDE_B)      // 67584
#define B_ROW_B    144              // 128B data + 16B pad
#define B_SPLIT_B  (128 * B_ROW_B)         // 18432
#define B_STAGE_B  (2 * B_SPLIT_B)         // 36864
#define B_OFF      (2 * A_SPLIT_B)         // 135168
#define CSQ_OFF    (B_OFF + 2 * B_STAGE_B) // 208896
#define ARG_SMEM   (CSQ_OFF + 8192)        // 217088

__global__ __launch_bounds__(256, 1)
void k_argmin_mma(const float* __restrict__ inp, float* __restrict__ out)
{
    extern __shared__ __align__(128) char smem[];
    uint32_t su = smem_to_u32(smem);
    int tid  = threadIdx.x;
    int w    = tid >> 5;
    int lane = tid & 31;

    int row0 = blockIdx.x * 128;
    int b = row0 >> 10, rem0 = row0 & 1023;

    // --- prologue: prefetch B stage 0 (tile 0, kc 0) ---
    const char* hib = (const char*)g_cbHi;
    const char* lob = (const char*)g_cbLo;
    {
#pragma unroll
        for (int i = 0; i < 4; ++i) {
            int q = tid + i * 256;              // 0..1023
            int code = q >> 3, kch = q & 7;
            uint32_t dst = su + B_OFF + (uint32_t)code * B_ROW_B + (uint32_t)kch * 16;
            const char* sh = hib + (size_t)code * 512 + kch * 16;
            const char* sl = lob + (size_t)code * 512 + kch * 16;
            CP_ASYNC16(dst, sh);
            CP_ASYNC16(dst + B_SPLIT_B, sl);
        }
        CP_COMMIT();
    }

    // --- csq -> smem (8 KB) ---
    {
        const float4* srcc = (const float4*)g_csq;
        float4* dstc = (float4*)(smem + CSQ_OFF);
        for (int i = tid; i < KCODES / 4; i += 256) dstc[i] = srcc[i];
    }

    // --- A convert: 128 rows x 256 d -> smem bf16 hi/lo ---
    {
        int row = tid & 127, half = tid >> 7;            // 2 threads per row
        const float* src = inp + (size_t)b * 262144 + rem0 + row;
        __nv_bfloat16* ah = (__nv_bfloat16*)smem + (size_t)row * A_STRIDE_E;
        __nv_bfloat16* al = ah + (A_SPLIT_B / 2);
#pragma unroll 4
        for (int i = 0; i < 128; ++i) {
            int d = half * 128 + i;
            float x = __ldg(src + (size_t)d * 1024);
            __nv_bfloat16 h = __float2bfloat16(x);
            __nv_bfloat16 l = __float2bfloat16(x - __bfloat162float(h));
            ah[d] = h;
            al[d] = l;
        }
    }
    __syncthreads();

    // per-thread constant fragment address components (CUTLASS-standard order):
    // A x4: lanes 0-7 m0(rows+0,k lo16B), 8-15 m1(rows+8), 16-23 m2(k+8), 24-31 m3
    uint32_t aOff = su + (uint32_t)w * (16u * A_STRIDE_B)
                  + (uint32_t)(lane & 15) * A_STRIDE_B
                  + (uint32_t)((lane >> 4) & 1) * 16u;
    // B x4 (n-tile pair): m0 codes+0 kLo, m1 codes+0 kHi, m2 codes+8 kLo, m3 codes+8 kHi
    uint32_t bOff = (uint32_t)((lane & 7) + ((lane & 16) ? 8 : 0)) * B_ROW_B
                  + (uint32_t)((lane & 8) ? 16 : 0);

    const float* csq_s = (const float*)(smem + CSQ_OFF);
    float s1r0 = g_xsq[row0 + w * 16 + (lane >> 2)];
    float s1r1 = g_xsq[row0 + w * 16 + (lane >> 2) + 8];

    float bv0 = 3.4e38f, bv1 = 3.4e38f;
    int   bi0 = 0,       bi1 = 0;

    float acc[64];   // 16 n-tiles x 4 (c0:(r,2q) c1:(r,2q+1) c2:(r+8,2q) c3:(r+8,2q+1))

    for (int s = 0; s < 64; ++s) {
        int kc = s & 3;

        // prefetch stage s+1
        if (s + 1 < 64) {
            int sn = s + 1;
            int tileC = (sn >> 2) * 128, kcN = sn & 3;
            uint32_t dstB = su + B_OFF + (uint32_t)((sn & 1)) * B_STAGE_B;
#pragma unroll
            for (int i = 0; i < 4; ++i) {
                int q = tid + i * 256;
                int code = q >> 3, kch = q & 7;
                uint32_t dst = dstB + (uint32_t)code * B_ROW_B + (uint32_t)kch * 16;
                const char* sh = hib + (size_t)(tileC + code) * 512 + kcN * 128 + kch * 16;
                const char* sl = lob + (size_t)(tileC + code) * 512 + kcN * 128 + kch * 16;
                CP_ASYNC16(dst, sh);
                CP_ASYNC16(dst + B_SPLIT_B, sl);
            }
        }
        CP_COMMIT();
        CP_WAIT1();          // stage s landed (<=1 group pending)
        __syncthreads();

        if (kc == 0) {
#pragma unroll
            for (int i = 0; i < 64; ++i) acc[i] = 0.f;
        }

        uint32_t Bst = su + B_OFF + (uint32_t)(s & 1) * B_STAGE_B + bOff;

#pragma unroll
        for (int ks2 = 0; ks2 < 4; ++ks2) {
            int ks = kc * 4 + ks2;                 // global k16-step 0..15
            uint32_t ah[4], al[4];
            LDM_X4(ah[0], ah[1], ah[2], ah[3], aOff + (uint32_t)ks * 32u);
            LDM_X4(al[0], al[1], al[2], al[3], aOff + A_SPLIT_B + (uint32_t)ks * 32u);
#pragma unroll
            for (int tp = 0; tp < 8; ++tp) {       // n-tile pairs (16 codes)
                uint32_t bh[4], bl[4];
                uint32_t bo = Bst + (uint32_t)tp * (16u * B_ROW_B) + (uint32_t)ks2 * 32u;
                LDM_X4(bh[0], bh[1], bh[2], bh[3], bo);
                LDM_X4(bl[0], bl[1], bl[2], bl[3], bo + B_SPLIT_B);
                float* A0 = &acc[(tp * 2 + 0) * 4];
                float* A1 = &acc[(tp * 2 + 1) * 4];
                MMA_BF16(A0, ah[0], ah[1], ah[2], ah[3], bh[0], bh[1]);  // hi*hi
                MMA_BF16(A0, ah[0], ah[1], ah[2], ah[3], bl[0], bl[1]);  // hi*lo
                MMA_BF16(A0, al[0], al[1], al[2], al[3], bh[0], bh[1]);  // lo*hi
                MMA_BF16(A1, ah[0], ah[1], ah[2], ah[3], bh[2], bh[3]);
                MMA_BF16(A1, ah[0], ah[1], ah[2], ah[3], bl[2], bl[3]);
                MMA_BF16(A1, al[0], al[1], al[2], al[3], bh[2], bh[3]);
            }
        }

        // epilogue at last k-chunk of the tile: dist = fl(fl(s1+csq)-2m),
        // strict-< ascending order == first-index argmin.
        if (kc == 3) {
            int codeBase = (s >> 2) * 128;
#pragma unroll
            for (int t = 0; t < 16; ++t) {
                int c0 = codeBase + t * 8 + 2 * (lane & 3);
                float2 cs2 = *(const float2*)&csq_s[c0];
                float dd;
                dd = __fsub_rn(__fadd_rn(s1r0, cs2.x), 2.0f * acc[t * 4 + 0]);
                if (dd < bv0) { bv0 = dd; bi0 = c0; }
                dd = __fsub_rn(__fadd_rn(s1r0, cs2.y), 2.0f * acc[t * 4 + 1]);
                if (dd < bv0) { bv0 = dd; bi0 = c0 + 1; }
                dd = __fsub_rn(__fadd_rn(s1r1, cs2.x), 2.0f * acc[t * 4 + 2]);
                if (dd < bv1) { bv1 = dd; bi1 = c0; }
                dd = __fsub_rn(__fadd_rn(s1r1, cs2.y), 2.0f * acc[t * 4 + 3]);
                if (dd < bv1) { bv1 = dd; bi1 = c0 + 1; }
            }
        }
        __syncthreads();   // all warps done with stage (s&1) before overwrite
    }

    // reduce across the 4 lanes of each row group (disjoint col sets; low-idx ties)
#pragma unroll
    for (int m = 1; m < 4; m <<= 1) {
        float ov = __shfl_xor_sync(0xffffffffu, bv0, m);
        int   oc = __shfl_xor_sync(0xffffffffu, bi0, m);
        if (ov < bv0 || (ov == bv0 && oc < bi0)) { bv0 = ov; bi0 = oc; }
        ov = __shfl_xor_sync(0xffffffffu, bv1, m);
        oc = __shfl_xor_sync(0xffffffffu, bi1, m);
        if (ov < bv1 || (ov == bv1 && oc < bi1)) { bv1 = ov; bi1 = oc; }
    }
    if ((lane & 3) == 0) {
        int r0 = row0 + w * 16 + (lane >> 2);
        g_idx[r0] = bi0;
        g_idx[r0 + 8] = bi1;
        out[OFF_IDX + r0] = (float)bi0;
        out[OFF_IDX + r0 + 8] = (float)bi1;
    }
}

// ===========================================================================
// Gather quantized vectors (straight-through, replicating reference rounding),
// write quant_out in [B,D,H,W] layout, accumulate SSE for the loss.
__global__ void k_gather(const float* __restrict__ inp,
                         const float* __restrict__ cb,
                         float* __restrict__ out)
{
    __shared__ int   sidx[128];
    __shared__ float red[256];
    int tid = threadIdx.x;
    int row0 = blockIdx.x * 128;
    if (tid < 128) sidx[tid] = g_idx[row0 + tid];
    __syncthreads();

    int b = row0 >> 10, rem0 = row0 & 1023;
    size_t base = (size_t)b * 262144 + rem0;
    int r  = tid & 127;
    int d0 = tid >> 7;   // 0 or 1
    const float* crow = cb + (size_t)sidx[r] * DIM;

    float s = 0.f;
#pragma unroll 4
    for (int d = d0; d < DIM; d += 2) {
        float q = __ldg(&crow[d]);
        size_t off = base + (size_t)d * 1024 + r;
        float x = inp[off];
        out[OFF_QUANT + off] = __fadd_rn(x, __fsub_rn(q, x));  // x + (q - x)
        float df = __fsub_rn(q, x);
        s = fmaf(df, df, s);
    }
    red[tid] = s;
    __syncthreads();
    for (int m = 128; m; m >>= 1) {
        if (tid < m) red[tid] += red[tid + m];
        __syncthreads();
    }
    if (tid == 0) {
        double v = (double)red[0] * 256.0;
        atomicAdd(&g_sse, (unsigned long long)(v + 0.5));  // deterministic fixed-point
    }
}

__global__ void k_hist()
{
    __shared__ int h[KCODES];
    for (int i = threadIdx.x; i < KCODES; i += 256) h[i] = 0;
    __syncthreads();
    for (int i = blockIdx.x * 256 + threadIdx.x; i < N_VEC; i += gridDim.x * 256)
        atomicAdd(&h[g_idx[i]], 1);
    __syncthreads();
    for (int i = threadIdx.x; i < KCODES; i += 256) {
        int c = h[i];
        if (c) atomicAdd(&g_cnt[i], c);
    }
}

__global__ void k_final(float* __restrict__ out)
{
    __shared__ float red[256];
    int tid = threadIdx.x;
    float s = 0.f;
    for (int k = tid; k < KCODES; k += 256) {
        float p = (float)g_cnt[k] * (1.0f / 65536.0f);
        s += p * logf(p + 1e-10f);
    }
    red[tid] = s;
    __syncthreads();
    for (int m = 128; m; m >>= 1) {
        if (tid < m) red[tid] += red[tid + m];
        __syncthreads();
    }
    if (tid == 0) {
        double sse = (double)g_sse * (1.0 / 256.0);
        out[OFF_LOSS] = (float)(1.25 * sse / 16777216.0);
        out[OFF_PERP] = expf(-red[0]);
    }
}

// ===========================================================================
extern "C" void kernel_launch(void* const* d_in, const int* in_sizes, int n_in,
                              void* d_out, int out_size)
{
    const float* inp = (const float*)d_in[0];   // [64,256,32,32] f32
    const float* cb  = (const float*)d_in[1];   // [2048,256] f32
    float* out = (float*)d_out;

    // Unconditional (idempotent, host-side, capture-legal) — no static guards.
    cudaFuncSetAttribute(k_argmin_mma, cudaFuncAttributeMaxDynamicSharedMemorySize, ARG_SMEM);

    k_init<<<8, 256>>>();
    k_split<<<KCODES, 256>>>(cb);
    k_csq<<<8, 256>>>(cb);
    k_xsq<<<512, 128>>>(inp);
    k_argmin_mma<<<512, 256, ARG_SMEM>>>(inp, out);
    k_gather<<<512, 256>>>(inp, cb, out);
    k_hist<<<64, 256>>>();
    k_final<<<1, 256>>>(out);
}

// round 8
// speedup vs baseline: 2.6465x; 1.2022x over previous
#include <cuda_runtime.h>
#include <cuda_bf16.h>
#include <math.h>
#include <stdint.h>

// ===========================================================================
// Problem constants
#define N_VEC   65536      // 64*32*32 vectors
#define DIM     256
#define KCODES  2048

// Output layout (float32, reference return order)
#define OFF_LOSS  0
#define OFF_QUANT 1
#define OFF_PERP  (1 + 64*256*32*32)     // 4194305
#define OFF_IDX   (OFF_PERP + 1)         // 4194306

// ===========================================================================
// PTX helpers (sm_90-baseline features only: mma.sync / ldmatrix / bulk TMA / mbarrier)
__device__ __forceinline__ uint32_t smem_to_u32(const void* p) {
    uint32_t a;
    asm("{ .reg .u64 t; cvta.to.shared.u64 t, %1; cvt.u32.u64 %0, t; }" : "=r"(a) : "l"(p));
    return a;
}
#define MBARRIER_INIT(mbar, cnt) \
    asm volatile("mbarrier.init.shared.b64 [%0], %1;" :: "r"((uint32_t)(mbar)), "r"((uint32_t)(cnt)) : "memory")
#define MBARRIER_EXPECT_TX(mbar, bytes) \
    asm volatile("mbarrier.arrive.expect_tx.shared.b64 _, [%0], %1;" \
        :: "r"((uint32_t)(mbar)), "r"((uint32_t)(bytes)) : "memory")
#define MBARRIER_WAIT_PARITY(mbar_addr, parity) do { \
    uint32_t _mbar = (uint32_t)(mbar_addr); \
    uint32_t _par = (uint32_t)(parity); \
    uint32_t _done; \
    asm volatile("{\n\t.reg .pred p;\n\t" \
        "mbarrier.try_wait.parity.acquire.cta.shared::cta.b64 p, [%1], %2;\n\t" \
        "selp.b32 %0, 1, 0, p;\n\t}" : "=r"(_done) : "r"(_mbar), "r"(_par) : "memory"); \
    if (!_done) { \
        asm volatile("{\n\t.reg .pred P1;\n\t" \
            "WL_%=:\n\t" \
            "mbarrier.try_wait.parity.acquire.cta.shared::cta.b64 P1, [%0], %1, 0x989680;\n\t" \
            "@P1 bra.uni WD_%=;\n\t" \
            "bra.uni WL_%=;\n\t" \
            "WD_%=:\n\t}" :: "r"(_mbar), "r"(_par) : "memory"); \
    } \
} while (0)
// 1-D bulk copy gmem -> smem with transaction-count completion (sm_90 baseline).
#define TMA_BULK_G2S(dst_smem, src_gmem, nbytes, mbar) \
    asm volatile("cp.async.bulk.shared::cluster.global.mbarrier::complete_tx::bytes [%0], [%1], %2, [%3];" \
        :: "r"((uint32_t)(dst_smem)), "l"(src_gmem), "r"((uint32_t)(nbytes)), "r"((uint32_t)(mbar)) : "memory")

#define LDM_X4(r0, r1, r2, r3, addr) \
    asm volatile("ldmatrix.sync.aligned.m8n8.x4.shared.b16 {%0,%1,%2,%3}, [%4];" \
        : "=r"(r0), "=r"(r1), "=r"(r2), "=r"(r3) : "r"(addr))
#define LDM_X4T(r0, r1, r2, r3, addr) \
    asm volatile("ldmatrix.sync.aligned.m8n8.x4.trans.shared.b16 {%0,%1,%2,%3}, [%4];" \
        : "=r"(r0), "=r"(r1), "=r"(r2), "=r"(r3) : "r"(addr))

#define MMA_BF16(d, a0, a1, a2, a3, b0, b1) \
    asm volatile("mma.sync.aligned.m16n8k16.row.col.f32.bf16.bf16.f32 " \
        "{%0,%1,%2,%3}, {%4,%5,%6,%7}, {%8,%9}, {%0,%1,%2,%3};" \
        : "+f"((d)[0]), "+f"((d)[1]), "+f"((d)[2]), "+f"((d)[3]) \
        : "r"(a0), "r"(a1), "r"(a2), "r"(a3), "r"(b0), "r"(b1))

// ===========================================================================
// Device scratch (static — no runtime allocation)
// B image pre-padded for direct bulk copy: per stage block (tile*4+kc) of
// 18432 B = 128 codes x (128 B data + 16 B pad).
#define B_ROW_B    144
#define B_ROW_E    72               // bf16 elems per padded row
#define B_BLOCK_E  (128 * B_ROW_E)  // 9216 elems = 18432 B per (tile,chunk)
__device__ __nv_bfloat16 g_cbHiP[64 * B_BLOCK_E];   // 1.125 MB
__device__ __nv_bfloat16 g_cbLoP[64 * B_BLOCK_E];   // 1.125 MB
__device__ float g_csq[KCODES];
__device__ int   g_idx[N_VEC];
__device__ unsigned long long g_sse;
__device__ int   g_cnt[KCODES];

// ===========================================================================
__global__ void k_init()
{
    int t = blockIdx.x * 256 + threadIdx.x;
    if (t == 0) g_sse = 0ULL;
    if (t < KCODES) g_cnt[t] = 0;
}

// Split codebook into bf16 hi/lo into the padded bulk-copy image, and compute
// ||c||^2 per code (block tree reduce — s2 ~2e-5, association error ~1e-11,
// negligible vs ulp(dist)=3e-5).
__global__ void k_split(const float* __restrict__ cb)
{
    __shared__ float red[256];
    int code = blockIdx.x;     // 0..2047
    int d    = threadIdx.x;    // 0..255
    float x = cb[code * DIM + d];
    __nv_bfloat16 h = __float2bfloat16(x);
    __nv_bfloat16 l = __float2bfloat16(x - __bfloat162float(h));
    int tile = code >> 7, r = code & 127, kc = d >> 6, j = d & 63;
    size_t off = (size_t)(tile * 4 + kc) * B_BLOCK_E + (size_t)r * B_ROW_E + j;
    g_cbHiP[off] = h;
    g_cbLoP[off] = l;

    red[d] = x * x;
    __syncthreads();
    for (int m = 128; m; m >>= 1) {
        if (d < m) red[d] += red[d + m];
        __syncthreads();
    }
    if (d == 0) g_csq[code] = red[0];
}

// ===========================================================================
// Fused bf16-split (Ootomo 3-pass) mma.sync GEMM + argmin.
// 512 CTAs x 256 thr (8 warps); 128 rows x all 2048 codes; warp w = rows [16w,16w+16).
// A stored K-MAJOR in smem (A^T[k][row], 272B stride) -> ldmatrix.x4.trans.
// B double-buffered, filled by 1-D bulk TMA (2 copies/stage), mbarrier-paced.
// 64 stages: stage s -> code tile (s>>2), k-chunk (s&3); B block index == s.
#define AT_STRIDE_B 272                       // 128 bf16 data (256B) + 16B pad
#define A_SPLIT_B   (256 * AT_STRIDE_B)       // 69632
#define A_TOTAL_B   (2 * A_SPLIT_B)           // 139264
#define B_SPLIT_B   18432
#define B_STAGE_B   36864
#define B_OFF       A_TOTAL_B                 // 139264
#define CSQ_OFF     (B_OFF + 2 * B_STAGE_B)   // 212992
#define S1_OFF      (CSQ_OFF + 8192)          // 221184
#define MB_OFF      (S1_OFF + 512)            // 221696
#define ARG_SMEM    (MB_OFF + 64)             // 221760

__global__ __launch_bounds__(256, 1)
void k_argmin_mma(const float* __restrict__ inp, float* __restrict__ out)
{
    extern __shared__ __align__(128) char smem[];
    uint32_t su = smem_to_u32(smem);
    int tid  = threadIdx.x;
    int w    = tid >> 5;
    int lane = tid & 31;

    int row0 = blockIdx.x * 128;
    int b = row0 >> 10, rem0 = row0 & 1023;

    // mbarrier init (one per stage buffer), then stage-0 bulk issue
    if (tid == 0) {
        MBARRIER_INIT(su + MB_OFF,     1);
        MBARRIER_INIT(su + MB_OFF + 8, 1);
    }
    __syncthreads();
    const char* hiP = (const char*)g_cbHiP;
    const char* loP = (const char*)g_cbLoP;
    if (tid == 0) {
        MBARRIER_EXPECT_TX(su + MB_OFF, B_STAGE_B);
        TMA_BULK_G2S(su + B_OFF,             hiP, B_SPLIT_B, su + MB_OFF);
        TMA_BULK_G2S(su + B_OFF + B_SPLIT_B, loP, B_SPLIT_B, su + MB_OFF);
    }

    // csq -> smem (8 KB)
    {
        const float4* srcc = (const float4*)g_csq;
        float4* dstc = (float4*)(smem + CSQ_OFF);
        for (int i = tid; i < KCODES / 4; i += 256) dstc[i] = srcc[i];
    }

    // --- A convert (K-major, vectorized) + fused ||x||^2 partials ---
    // Thread (kb=tid>>4, rb=tid&15): k = kb+16i (16 iters), rows rb*8..rb*8+7.
    {
        const float* srcb = inp + (size_t)b * 262144 + rem0;
        int kb = tid >> 4, rb = tid & 15;
        float pacc[8];
#pragma unroll
        for (int j = 0; j < 8; ++j) pacc[j] = 0.f;
#pragma unroll 2
        for (int i = 0; i < 16; ++i) {
            int k = kb + (i << 4);
            const float4* p = (const float4*)(srcb + (size_t)k * 1024 + rb * 8);
            float4 v0 = __ldg(p), v1 = __ldg(p + 1);
            float xv[8] = {v0.x, v0.y, v0.z, v0.w, v1.x, v1.y, v1.z, v1.w};
            uint32_t hp[4], lp[4];
#pragma unroll
            for (int q = 0; q < 4; ++q) {
                float a0 = xv[2 * q], a1 = xv[2 * q + 1];
                __nv_bfloat16 h0 = __float2bfloat16(a0), h1 = __float2bfloat16(a1);
                __nv_bfloat16 l0 = __float2bfloat16(a0 - __bfloat162float(h0));
                __nv_bfloat16 l1 = __float2bfloat16(a1 - __bfloat162float(h1));
                __nv_bfloat162 ph, pl;
                ph.x = h0; ph.y = h1; pl.x = l0; pl.y = l1;
                hp[q] = *(uint32_t*)&ph;
                lp[q] = *(uint32_t*)&pl;
                pacc[2 * q]     = fmaf(a0, a0, pacc[2 * q]);
                pacc[2 * q + 1] = fmaf(a1, a1, pacc[2 * q + 1]);
            }
            *(uint4*)(smem + k * AT_STRIDE_B + rb * 16) =
                make_uint4(hp[0], hp[1], hp[2], hp[3]);
            *(uint4*)(smem + A_SPLIT_B + k * AT_STRIDE_B + rb * 16) =
                make_uint4(lp[0], lp[1], lp[2], lp[3]);
        }
        // partials live in B buffer 1 (not written until mainloop iter 0)
        float* part = (float*)(smem + B_OFF + B_STAGE_B);
#pragma unroll
        for (int j = 0; j < 8; ++j) part[kb * 128 + rb * 8 + j] = pacc[j];
    }
    __syncthreads();
    if (tid < 128) {
        const float* part = (const float*)(smem + B_OFF + B_STAGE_B);
        float s = 0.f;
#pragma unroll
        for (int g = 0; g < 16; ++g) s += part[g * 128 + tid];   // fixed order
        ((float*)(smem + S1_OFF))[tid] = s;
    }
    __syncthreads();

    // per-thread constant fragment addresses
    // A (k-major, ldmatrix.trans): m0..m3 = (k0,r0),(k0,r8),(k8,r0),(k8,r8)
    uint32_t aHiBase = su + ((lane & 7) + ((lane & 16) >> 1)) * AT_STRIDE_B
                     + (uint32_t)(w * 16 + ((lane & 8) ? 8 : 0)) * 2u;
    uint32_t aLoBase = aHiBase + A_SPLIT_B;
    // B (n-major rows, non-trans; validated in R7)
    uint32_t bOff = (uint32_t)((lane & 7) + ((lane & 16) ? 8 : 0)) * B_ROW_B
                  + (uint32_t)((lane & 8) ? 16 : 0);

    const float* csq_s = (const float*)(smem + CSQ_OFF);
    const float* s1s   = (const float*)(smem + S1_OFF);
    float s1r0 = s1s[w * 16 + (lane >> 2)];
    float s1r1 = s1s[w * 16 + (lane >> 2) + 8];

    float bv0 = 3.4e38f, bv1 = 3.4e38f;
    int   bi0 = 0,       bi1 = 0;
    float acc[64];   // 16 n-tiles x 4: c0(r,2q) c1(r,2q+1) c2(r+8,2q) c3(r+8,2q+1)

    for (int s = 0; s < 64; ++s) {
        int kc = s & 3;

        // issue bulk for stage s+1 (buffer (s+1)&1 was drained by the barrier
        // at the end of iteration s-1)
        if (s + 1 < 64 && tid == 0) {
            int sn = s + 1;
            uint32_t mb  = su + MB_OFF + (uint32_t)(sn & 1) * 8u;
            uint32_t dst = su + B_OFF + (uint32_t)(sn & 1) * B_STAGE_B;
            size_t   srcoff = (size_t)sn * B_SPLIT_B;
            MBARRIER_EXPECT_TX(mb, B_STAGE_B);
            TMA_BULK_G2S(dst,             hiP + srcoff, B_SPLIT_B, mb);
            TMA_BULK_G2S(dst + B_SPLIT_B, loP + srcoff, B_SPLIT_B, mb);
        }

        // wait stage s data
        MBARRIER_WAIT_PARITY(su + MB_OFF + (s & 1) * 8, (s >> 1) & 1);

        if (kc == 0) {
#pragma unroll
            for (int i = 0; i < 64; ++i) acc[i] = 0.f;
        }

        uint32_t Bst = su + B_OFF + (uint32_t)(s & 1) * B_STAGE_B + bOff;

#pragma unroll
        for (int ks2 = 0; ks2 < 4; ++ks2) {
            int ks = kc * 4 + ks2;                 // global k16-step 0..15
            uint32_t ah[4], al[4];
            LDM_X4T(ah[0], ah[1], ah[2], ah[3], aHiBase + (uint32_t)ks * (16u * AT_STRIDE_B));
            LDM_X4T(al[0], al[1], al[2], al[3], aLoBase + (uint32_t)ks * (16u * AT_STRIDE_B));
#pragma unroll
            for (int tp = 0; tp < 8; ++tp) {       // n-tile pairs (16 codes)
                uint32_t bh[4], bl[4];
                uint32_t bo = Bst + (uint32_t)tp * (16u * B_ROW_B) + (uint32_t)ks2 * 32u;
                LDM_X4(bh[0], bh[1], bh[2], bh[3], bo);
                LDM_X4(bl[0], bl[1], bl[2], bl[3], bo + B_SPLIT_B);
                float* A0 = &acc[(tp * 2 + 0) * 4];
                float* A1 = &acc[(tp * 2 + 1) * 4];
                MMA_BF16(A0, ah[0], ah[1], ah[2], ah[3], bh[0], bh[1]);  // hi*hi
                MMA_BF16(A0, ah[0], ah[1], ah[2], ah[3], bl[0], bl[1]);  // hi*lo
                MMA_BF16(A0, al[0], al[1], al[2], al[3], bh[0], bh[1]);  // lo*hi
                MMA_BF16(A1, ah[0], ah[1], ah[2], ah[3], bh[2], bh[3]);
                MMA_BF16(A1, ah[0], ah[1], ah[2], ah[3], bl[2], bl[3]);
                MMA_BF16(A1, al[0], al[1], al[2], al[3], bh[2], bh[3]);
            }
        }

        // epilogue at last k-chunk: dist = fl(fl(s1+csq)-2m), strict-< ascending
        if (kc == 3) {
            int codeBase = (s >> 2) * 128;
#pragma unroll
            for (int t = 0; t < 16; ++t) {
                int c0 = codeBase + t * 8 + 2 * (lane & 3);
                float2 cs2 = *(const float2*)&csq_s[c0];
                float dd;
                dd = __fsub_rn(__fadd_rn(s1r0, cs2.x), 2.0f * acc[t * 4 + 0]);
                if (dd < bv0) { bv0 = dd; bi0 = c0; }
                dd = __fsub_rn(__fadd_rn(s1r0, cs2.y), 2.0f * acc[t * 4 + 1]);
                if (dd < bv0) { bv0 = dd; bi0 = c0 + 1; }
                dd = __fsub_rn(__fadd_rn(s1r1, cs2.x), 2.0f * acc[t * 4 + 2]);
                if (dd < bv1) { bv1 = dd; bi1 = c0; }
                dd = __fsub_rn(__fadd_rn(s1r1, cs2.y), 2.0f * acc[t * 4 + 3]);
                if (dd < bv1) { bv1 = dd; bi1 = c0 + 1; }
            }
        }
        __syncthreads();   // all warps done reading buffer (s&1) before reuse
    }

    // reduce across 4 lanes per row group (disjoint col sets; low-idx ties)
#pragma unroll
    for (int m = 1; m < 4; m <<= 1) {
        float ov = __shfl_xor_sync(0xffffffffu, bv0, m);
        int   oc = __shfl_xor_sync(0xffffffffu, bi0, m);
        if (ov < bv0 || (ov == bv0 && oc < bi0)) { bv0 = ov; bi0 = oc; }
        ov = __shfl_xor_sync(0xffffffffu, bv1, m);
        oc = __shfl_xor_sync(0xffffffffu, bi1, m);
        if (ov < bv1 || (ov == bv1 && oc < bi1)) { bv1 = ov; bi1 = oc; }
    }
    if ((lane & 3) == 0) {
        int r0 = row0 + w * 16 + (lane >> 2);
        g_idx[r0] = bi0;
        g_idx[r0 + 8] = bi1;
        out[OFF_IDX + r0] = (float)bi0;
        out[OFF_IDX + r0 + 8] = (float)bi1;
    }
}

// ===========================================================================
// Gather quantized vectors (straight-through, replicating reference rounding),
// write quant_out in [B,D,H,W] layout, accumulate SSE for the loss.
__global__ void k_gather(const float* __restrict__ inp,
                         const float* __restrict__ cb,
                         float* __restrict__ out)
{
    __shared__ int   sidx[128];
    __shared__ float red[256];
    int tid = threadIdx.x;
    int row0 = blockIdx.x * 128;
    if (tid < 128) sidx[tid] = g_idx[row0 + tid];
    __syncthreads();

    int b = row0 >> 10, rem0 = row0 & 1023;
    size_t base = (size_t)b * 262144 + rem0;
    int r  = tid & 127;
    int d0 = tid >> 7;   // 0 or 1
    const float* crow = cb + (size_t)sidx[r] * DIM;

    float s = 0.f;
#pragma unroll 4
    for (int d = d0; d < DIM; d += 2) {
        float q = __ldg(&crow[d]);
        size_t off = base + (size_t)d * 1024 + r;
        float x = inp[off];
        out[OFF_QUANT + off] = __fadd_rn(x, __fsub_rn(q, x));  // x + (q - x)
        float df = __fsub_rn(q, x);
        s = fmaf(df, df, s);
    }
    red[tid] = s;
    __syncthreads();
    for (int m = 128; m; m >>= 1) {
        if (tid < m) red[tid] += red[tid + m];
        __syncthreads();
    }
    if (tid == 0) {
        double v = (double)red[0] * 256.0;
        atomicAdd(&g_sse, (unsigned long long)(v + 0.5));  // deterministic fixed-point
    }
}

__global__ void k_hist()
{
    __shared__ int h[KCODES];
    for (int i = threadIdx.x; i < KCODES; i += 256) h[i] = 0;
    __syncthreads();
    for (int i = blockIdx.x * 256 + threadIdx.x; i < N_VEC; i += gridDim.x * 256)
        atomicAdd(&h[g_idx[i]], 1);
    __syncthreads();
    for (int i = threadIdx.x; i < KCODES; i += 256) {
        int c = h[i];
        if (c) atomicAdd(&g_cnt[i], c);
    }
}

__global__ void k_final(float* __restrict__ out)
{
    __shared__ float red[256];
    int tid = threadIdx.x;
    float s = 0.f;
    for (int k = tid; k < KCODES; k += 256) {
        float p = (float)g_cnt[k] * (1.0f / 65536.0f);
        s += p * logf(p + 1e-10f);
    }
    red[tid] = s;
    __syncthreads();
    for (int m = 128; m; m >>= 1) {
        if (tid < m) red[tid] += red[tid + m];
        __syncthreads();
    }
    if (tid == 0) {
        double sse = (double)g_sse * (1.0 / 256.0);
        out[OFF_LOSS] = (float)(1.25 * sse / 16777216.0);
        out[OFF_PERP] = expf(-red[0]);
    }
}

// ===========================================================================
extern "C" void kernel_launch(void* const* d_in, const int* in_sizes, int n_in,
                              void* d_out, int out_size)
{
    const float* inp = (const float*)d_in[0];   // [64,256,32,32] f32
    const float* cb  = (const float*)d_in[1];   // [2048,256] f32
    float* out = (float*)d_out;

    // Unconditional (idempotent, host-side, capture-legal) — no static guards.
    cudaFuncSetAttribute(k_argmin_mma, cudaFuncAttributeMaxDynamicSharedMemorySize, ARG_SMEM);

    k_init<<<8, 256>>>();
    k_split<<<KCODES, 256>>>(cb);
    k_argmin_mma<<<512, 256, ARG_SMEM>>>(inp, out);
    k_gather<<<512, 256>>>(inp, cb, out);
    k_hist<<<64, 256>>>();
    k_final<<<1, 256>>>(out);
}